// round 6
// baseline (speedup 1.0000x reference)
#include <cuda_runtime.h>
#include <cuda_bf16.h>
#include <math.h>
#include <stdint.h>

#define SEQLEN  4096
#define DMODEL  2048
#define DINNER  4096
#define DSTATE  128
#define NHEADS  64
#define HEADDIM 64
#define CONVDIM 4352
#define DPROJ   8512

// ---------------- scratch (device globals; no allocation allowed) ------------
__device__ float g_zxbcdt[(size_t)SEQLEN * DPROJ];   // in_proj output
__device__ float g_xBC[(size_t)SEQLEN * CONVDIM];    // conv+silu output
__device__ float g_dt[(size_t)SEQLEN * NHEADS];      // softplus(dt)
__device__ float g_dA[(size_t)SEQLEN * NHEADS];      // exp(dt * A)
__device__ float g_y[(size_t)SEQLEN * DINNER];       // scan output (+D skip)
__device__ float g_yn[(size_t)SEQLEN * DINNER];      // gated+normed (tf32-rounded)
__device__ float g_ur[(size_t)SEQLEN * DMODEL];      // tf32-rounded u
__device__ float g_w1r[(size_t)DPROJ * DMODEL];      // tf32-rounded in_proj_w
__device__ float g_w2r[(size_t)DMODEL * DINNER];     // tf32-rounded out_proj_w

__device__ __forceinline__ uint32_t smem_u32(const void* p) {
    uint32_t a;
    asm("{ .reg .u64 t; cvta.to.shared.u64 t, %1; cvt.u32.u64 %0, t; }"
        : "=r"(a) : "l"(p));
    return a;
}
__device__ __forceinline__ unsigned f2tf32(float v) {
    unsigned r;
    asm volatile("cvt.rna.tf32.f32 %0, %1;" : "=r"(r) : "f"(v));
    return r;
}
__device__ __forceinline__ void cp16(uint32_t dst, const void* src, int sz) {
    asm volatile("cp.async.cg.shared.global [%0], [%1], 16, %2;"
                 :: "r"(dst), "l"(src), "r"(sz) : "memory");
}

// ============ tf32 mma.sync GEMM, cp.async 3-stage: C = A[M,K] * B[N,K]^T ====
// Inputs A,B must be pre-rounded to tf32-representable floats.
// Tile 128x128x32, 256 threads (8 warps, each 64x32), M%128==0, K%32==0.
#define A_BYTES 16384                       // 128 * 32 * 4
#define B_BYTES 16384                       // 128 * 32 * 4
#define STG     (A_BYTES + B_BYTES)         // 32768 per stage
#define NSTAGE  3
#define GSMEM   (NSTAGE * STG)              // 98304

__global__ __launch_bounds__(256, 2)
void mma2_gemm(const float* __restrict__ A, const float* __restrict__ B,
               float* __restrict__ C, int M, int N, int K)
{
    extern __shared__ char smem_raw[];
    const uint32_t sb = smem_u32(smem_raw);
    const int tid  = threadIdx.x;
    const int bm   = blockIdx.y * 128;
    const int bn   = blockIdx.x * 128;
    const int wid  = tid >> 5;
    const int lane = tid & 31;
    const int g    = lane >> 2;
    const int c    = lane & 3;
    const int wm   = (wid & 1) * 64;
    const int wn   = (wid >> 1) * 32;

    float acc[4][4][4];
#pragma unroll
    for (int i = 0; i < 4; i++)
#pragma unroll
        for (int j = 0; j < 4; j++)
#pragma unroll
            for (int r = 0; r < 4; r++) acc[i][j][r] = 0.f;

    // cp.async coords: chunk q -> row q>>3, k-granule q&7 (coalesced GMEM)
    const int niter = K >> 5;

    auto prefetch = [&](int it) {
        const int k0 = it << 5;
        const uint32_t st = sb + (it % NSTAGE) * STG;
#pragma unroll
        for (int j = 0; j < 4; j++) {
            const int q = tid + 256 * j;
            const int m = q >> 3, k4 = q & 7;
            cp16(st + k4 * 2048 + m * 16,
                 &A[(size_t)(bm + m) * K + k0 + k4 * 4], 16);
        }
#pragma unroll
        for (int j = 0; j < 4; j++) {
            const int q = tid + 256 * j;
            const int n = q >> 3, k4 = q & 7;
            const int ng = bn + n;
            const int nc = (ng < N) ? ng : (N - 1);
            cp16(st + A_BYTES + k4 * 2048 + n * 16,
                 &B[(size_t)nc * K + k0 + k4 * 4], (ng < N) ? 16 : 0);
        }
        asm volatile("cp.async.commit_group;" ::: "memory");
    };

    prefetch(0);
    if (niter > 1) prefetch(1); else asm volatile("cp.async.commit_group;" ::: "memory");

#pragma unroll 1
    for (int i = 0; i < niter; i++) {
        asm volatile("cp.async.wait_group 1;" ::: "memory");
        __syncthreads();
        if (i + 2 < niter) prefetch(i + 2);
        else asm volatile("cp.async.commit_group;" ::: "memory");

        const uint32_t sA = sb + (i % NSTAGE) * STG;
        const uint32_t sB = sA + A_BYTES;
#pragma unroll
        for (int ks = 0; ks < 4; ks++) {
            uint32_t a[4][4];
#pragma unroll
            for (int mi = 0; mi < 4; mi++) {
                const uint32_t ab = sA + (2 * ks) * 2048 + (wm + mi * 16 + g) * 16 + c * 4;
                asm volatile("ld.shared.b32 %0, [%1];" : "=r"(a[mi][0]) : "r"(ab));
                asm volatile("ld.shared.b32 %0, [%1];" : "=r"(a[mi][1]) : "r"(ab + 128));
                asm volatile("ld.shared.b32 %0, [%1];" : "=r"(a[mi][2]) : "r"(ab + 2048));
                asm volatile("ld.shared.b32 %0, [%1];" : "=r"(a[mi][3]) : "r"(ab + 2176));
            }
#pragma unroll
            for (int ni = 0; ni < 4; ni++) {
                const uint32_t bb = sB + (2 * ks) * 2048 + (wn + ni * 8 + g) * 16 + c * 4;
                uint32_t b0, b1;
                asm volatile("ld.shared.b32 %0, [%1];" : "=r"(b0) : "r"(bb));
                asm volatile("ld.shared.b32 %0, [%1];" : "=r"(b1) : "r"(bb + 2048));
#pragma unroll
                for (int mi = 0; mi < 4; mi++) {
                    asm volatile(
                        "mma.sync.aligned.m16n8k8.row.col.f32.tf32.tf32.f32 "
                        "{%0,%1,%2,%3}, {%4,%5,%6,%7}, {%8,%9}, {%0,%1,%2,%3};"
                        : "+f"(acc[mi][ni][0]), "+f"(acc[mi][ni][1]),
                          "+f"(acc[mi][ni][2]), "+f"(acc[mi][ni][3])
                        : "r"(a[mi][0]), "r"(a[mi][1]), "r"(a[mi][2]), "r"(a[mi][3]),
                          "r"(b0), "r"(b1));
                }
            }
        }
    }

#pragma unroll
    for (int mi = 0; mi < 4; mi++) {
        const int row0 = bm + wm + mi * 16 + g;
#pragma unroll
        for (int ni = 0; ni < 4; ni++) {
            const int col = bn + wn + ni * 8 + c * 2;
            if (col < N) {
                *reinterpret_cast<float2*>(&C[(size_t)row0 * N + col]) =
                    make_float2(acc[mi][ni][0], acc[mi][ni][1]);
                *reinterpret_cast<float2*>(&C[(size_t)(row0 + 8) * N + col]) =
                    make_float2(acc[mi][ni][2], acc[mi][ni][3]);
            }
        }
    }
}

// ---------------- tf32 pre-rounding (RNA) ------------------------------------
__global__ void round_tf32_kernel(const float4* __restrict__ src,
                                  float4* __restrict__ dst, int n4)
{
    const int i = blockIdx.x * blockDim.x + threadIdx.x;
    if (i >= n4) return;
    float4 v = src[i];
    dst[i] = make_float4(__uint_as_float(f2tf32(v.x)),
                         __uint_as_float(f2tf32(v.y)),
                         __uint_as_float(f2tf32(v.z)),
                         __uint_as_float(f2tf32(v.w)));
}

// ---------------- depthwise causal conv(4) + SiLU ----------------------------
__global__ void conv_silu_kernel(const float* __restrict__ zx,
                                 const float* __restrict__ cw,
                                 const float* __restrict__ cb,
                                 float* __restrict__ xBC)
{
    const int idx = blockIdx.x * blockDim.x + threadIdx.x;
    if (idx >= SEQLEN * CONVDIM) return;
    const int l = idx / CONVDIM;
    const int c = idx - l * CONVDIM;
    float a = cb[c];
    const float* col = zx + DINNER + c;
#pragma unroll
    for (int t = 0; t < 4; t++) {
        const int ll = l - 3 + t;
        if (ll >= 0) a = fmaf(col[(size_t)ll * DPROJ], cw[c * 4 + t], a);
    }
    const float sg = 1.f / (1.f + expf(-a));
    xBC[idx] = a * sg;
}

// ---------------- dt = softplus(raw + bias), dA = exp(dt * A) ----------------
__global__ void dt_kernel(const float* __restrict__ zx,
                          const float* __restrict__ dt_bias,
                          const float* __restrict__ A_log,
                          float* __restrict__ dt, float* __restrict__ dA)
{
    const int idx = blockIdx.x * blockDim.x + threadIdx.x;
    if (idx >= SEQLEN * NHEADS) return;
    const int l = idx >> 6;
    const int h = idx & 63;
    const float v = zx[(size_t)l * DPROJ + DINNER + CONVDIM + h] + dt_bias[h];
    const float d = (v > 20.f) ? v : log1pf(expf(v));
    dt[idx] = d;
    dA[idx] = expf(-d * expf(A_log[h]));
}

// ---------------- sequential selective scan ----------------------------------
__global__ __launch_bounds__(128)
void scan_kernel(const float* __restrict__ xBC, const float* __restrict__ dtv,
                 const float* __restrict__ dAv, const float* __restrict__ Dvec,
                 float* __restrict__ y)
{
    const int h    = blockIdx.x >> 2;
    const int pblk = blockIdx.x & 3;
    const int tid  = threadIdx.x;
    const int pl   = tid >> 3;
    const int ng   = tid & 7;
    const int p    = pblk * 16 + pl;
    const float Dh = Dvec[h];

    __shared__ float sB[8][128];
    __shared__ float sC[8][128];
    __shared__ float sx[8][16];
    __shared__ float sdt[8];
    __shared__ float sda[8];

    float s[16];
#pragma unroll
    for (int j = 0; j < 16; j++) s[j] = 0.f;

    for (int l0 = 0; l0 < SEQLEN; l0 += 8) {
        __syncthreads();
#pragma unroll
        for (int k = 0; k < 8; k++) {
            const float* row = xBC + (size_t)(l0 + k) * CONVDIM;
            sB[k][tid] = row[DINNER + tid];
            sC[k][tid] = row[DINNER + DSTATE + tid];
        }
        {
            const int tt = tid >> 4, pp = tid & 15;
            sx[tt][pp] = xBC[(size_t)(l0 + tt) * CONVDIM + h * HEADDIM + pblk * 16 + pp];
        }
        if (tid < 8)       sdt[tid]     = dtv[(l0 + tid) * NHEADS + h];
        else if (tid < 16) sda[tid - 8] = dAv[(l0 + tid - 8) * NHEADS + h];
        __syncthreads();

#pragma unroll
        for (int t = 0; t < 8; t++) {
            const float dtl = sdt[t];
            const float e   = sda[t];
            const float xv  = sx[t][pl];
            const float xp  = xv * dtl;
            float accv = 0.f;
#pragma unroll
            for (int j = 0; j < 16; j++) {
                const int n = ng + (j << 3);
                const float sv = fmaf(s[j], e, xp * sB[t][n]);
                s[j] = sv;
                accv = fmaf(sC[t][n], sv, accv);
            }
            accv += __shfl_xor_sync(0xffffffffu, accv, 1);
            accv += __shfl_xor_sync(0xffffffffu, accv, 2);
            accv += __shfl_xor_sync(0xffffffffu, accv, 4);
            if (ng == 0)
                y[(size_t)(l0 + t) * DINNER + h * HEADDIM + p] = accv + xv * Dh;
        }
    }
}

// -------- gate (y * silu(z)) + RMSNorm, output pre-rounded to tf32 -----------
__global__ __launch_bounds__(256)
void gate_norm_kernel(const float* __restrict__ y, const float* __restrict__ zx,
                      const float* __restrict__ nw, float* __restrict__ yn)
{
    __shared__ float buf[DINNER];
    __shared__ float red[8];
    const int l = blockIdx.x, tid = threadIdx.x;
    const float* yrow = y + (size_t)l * DINNER;
    const float* zrow = zx + (size_t)l * DPROJ;

    float part = 0.f;
    for (int i = tid; i < DINNER; i += 256) {
        const float z = zrow[i];
        const float gg = z / (1.f + expf(-z));
        const float v = yrow[i] * gg;
        buf[i] = v;
        part = fmaf(v, v, part);
    }
#pragma unroll
    for (int o = 16; o; o >>= 1) part += __shfl_xor_sync(0xffffffffu, part, o);
    if ((tid & 31) == 0) red[tid >> 5] = part;
    __syncthreads();
    if (tid < 8) {
        float v = red[tid];
#pragma unroll
        for (int o = 4; o; o >>= 1) v += __shfl_xor_sync(0xffu, v, o);
        if (tid == 0) red[0] = v;
    }
    __syncthreads();
    const float r = rsqrtf(red[0] / (float)DINNER + 1e-5f);
    for (int i = tid; i < DINNER; i += 256)
        yn[(size_t)l * DINNER + i] =
            __uint_as_float(f2tf32(buf[i] * r * nw[i]));
}

// ---------------- launcher ---------------------------------------------------
extern "C" void kernel_launch(void* const* d_in, const int* in_sizes, int n_in,
                              void* d_out, int out_size)
{
    const float* u          = (const float*)d_in[0];
    const float* in_proj_w  = (const float*)d_in[1];
    const float* conv_w     = (const float*)d_in[2];
    const float* conv_b     = (const float*)d_in[3];
    const float* dt_bias    = (const float*)d_in[4];
    const float* A_log      = (const float*)d_in[5];
    const float* Dvec       = (const float*)d_in[6];
    const float* norm_w     = (const float*)d_in[7];
    const float* out_proj_w = (const float*)d_in[8];
    float* out = (float*)d_out;

    float *zx, *xBC, *dt, *dA, *y, *yn, *ur, *w1r, *w2r;
    cudaGetSymbolAddress((void**)&zx,  g_zxbcdt);
    cudaGetSymbolAddress((void**)&xBC, g_xBC);
    cudaGetSymbolAddress((void**)&dt,  g_dt);
    cudaGetSymbolAddress((void**)&dA,  g_dA);
    cudaGetSymbolAddress((void**)&y,   g_y);
    cudaGetSymbolAddress((void**)&yn,  g_yn);
    cudaGetSymbolAddress((void**)&ur,  g_ur);
    cudaGetSymbolAddress((void**)&w1r, g_w1r);
    cudaGetSymbolAddress((void**)&w2r, g_w2r);

    cudaFuncSetAttribute(mma2_gemm,
                         cudaFuncAttributeMaxDynamicSharedMemorySize, GSMEM);

    // 0) pre-round activations + weights to tf32-representable fp32
    {
        const int n4u = SEQLEN * DMODEL / 4;
        const int n41 = DPROJ * DMODEL / 4;
        const int n42 = DMODEL * DINNER / 4;
        round_tf32_kernel<<<(n4u + 255) / 256, 256>>>((const float4*)u,  (float4*)ur,  n4u);
        round_tf32_kernel<<<(n41 + 255) / 256, 256>>>((const float4*)in_proj_w, (float4*)w1r, n41);
        round_tf32_kernel<<<(n42 + 255) / 256, 256>>>((const float4*)out_proj_w, (float4*)w2r, n42);
    }

    // 1) zxbcdt = u @ in_proj_w^T   (4096 x 8512, K=2048)
    mma2_gemm<<<dim3((DPROJ + 127) / 128, SEQLEN / 128), 256, GSMEM>>>(
        ur, w1r, zx, SEQLEN, DPROJ, DMODEL);

    // 2) causal depthwise conv + SiLU
    conv_silu_kernel<<<(SEQLEN * CONVDIM + 255) / 256, 256>>>(
        zx, conv_w, conv_b, xBC);

    // 3) dt / decay precompute
    dt_kernel<<<(SEQLEN * NHEADS + 255) / 256, 256>>>(
        zx, dt_bias, A_log, dt, dA);

    // 4) selective scan (+ D skip)
    scan_kernel<<<NHEADS * 4, 128>>>(xBC, dt, dA, Dvec, y);

    // 5) gate + RMSNorm (emits tf32-rounded yn)
    gate_norm_kernel<<<SEQLEN, 256>>>(y, zx, norm_w, yn);

    // 6) out = yn @ out_proj_w^T   (4096 x 2048, K=4096)
    mma2_gemm<<<dim3(DMODEL / 128, SEQLEN / 128), 256, GSMEM>>>(
        yn, w2r, out, SEQLEN, DMODEL, DINNER);
}

// round 9
// speedup vs baseline: 1.1990x; 1.1990x over previous
#include <cuda_runtime.h>
#include <cuda_bf16.h>
#include <math.h>
#include <stdint.h>

#define SEQLEN  4096
#define DMODEL  2048
#define DINNER  4096
#define DSTATE  128
#define NHEADS  64
#define HEADDIM 64
#define CONVDIM 4352
#define DPROJ   8512
#define CHUNK   256
#define NCHUNK  (SEQLEN / CHUNK)   // 16

// ---------------- scratch (device globals; no allocation allowed) ------------
__device__ float g_zxbcdt[(size_t)SEQLEN * DPROJ];
__device__ float g_xBC[(size_t)SEQLEN * CONVDIM];
__device__ float g_dt[(size_t)SEQLEN * NHEADS];
__device__ float g_dA[(size_t)SEQLEN * NHEADS];
__device__ float g_y[(size_t)SEQLEN * DINNER];
__device__ float g_yn[(size_t)SEQLEN * DINNER];
__device__ float g_ur[(size_t)SEQLEN * DMODEL];
__device__ float g_w1r[(size_t)DPROJ * DMODEL];
__device__ float g_w2r[(size_t)DMODEL * DINNER];
__device__ float g_st[(size_t)NHEADS * NCHUNK * HEADDIM * DSTATE]; // chunk states
__device__ float g_T[NCHUNK * NHEADS];                             // chunk decay

__device__ __forceinline__ uint32_t smem_u32(const void* p) {
    uint32_t a;
    asm("{ .reg .u64 t; cvta.to.shared.u64 t, %1; cvt.u32.u64 %0, t; }"
        : "=r"(a) : "l"(p));
    return a;
}
__device__ __forceinline__ unsigned f2tf32(float v) {
    unsigned r;
    asm volatile("cvt.rna.tf32.f32 %0, %1;" : "=r"(r) : "f"(v));
    return r;
}
__device__ __forceinline__ void cp16(uint32_t dst, const void* src, int sz) {
    asm volatile("cp.async.cg.shared.global [%0], [%1], 16, %2;"
                 :: "r"(dst), "l"(src), "r"(sz) : "memory");
}

// ============ tf32 mma.sync GEMM, cp.async 3-stage: C = A[M,K] * B[N,K]^T ====
#define A_BYTES 16384
#define B_BYTES 16384
#define STG     (A_BYTES + B_BYTES)
#define NSTAGE  3
#define GSMEM   (NSTAGE * STG)

__global__ __launch_bounds__(256, 2)
void mma2_gemm(const float* __restrict__ A, const float* __restrict__ B,
               float* __restrict__ C, int M, int N, int K)
{
    extern __shared__ char smem_raw[];
    const uint32_t sb = smem_u32(smem_raw);
    const int tid  = threadIdx.x;
    const int bm   = blockIdx.y * 128;
    const int bn   = blockIdx.x * 128;
    const int wid  = tid >> 5;
    const int lane = tid & 31;
    const int g    = lane >> 2;
    const int c    = lane & 3;
    const int wm   = (wid & 1) * 64;
    const int wn   = (wid >> 1) * 32;

    float acc[4][4][4];
#pragma unroll
    for (int i = 0; i < 4; i++)
#pragma unroll
        for (int j = 0; j < 4; j++)
#pragma unroll
            for (int r = 0; r < 4; r++) acc[i][j][r] = 0.f;

    const int niter = K >> 5;

    auto prefetch = [&](int it) {
        const int k0 = it << 5;
        const uint32_t st = sb + (it % NSTAGE) * STG;
#pragma unroll
        for (int j = 0; j < 4; j++) {
            const int q = tid + 256 * j;
            const int m = q >> 3, k4 = q & 7;
            cp16(st + k4 * 2048 + m * 16,
                 &A[(size_t)(bm + m) * K + k0 + k4 * 4], 16);
        }
#pragma unroll
        for (int j = 0; j < 4; j++) {
            const int q = tid + 256 * j;
            const int n = q >> 3, k4 = q & 7;
            const int ng = bn + n;
            const int nc = (ng < N) ? ng : (N - 1);
            cp16(st + A_BYTES + k4 * 2048 + n * 16,
                 &B[(size_t)nc * K + k0 + k4 * 4], (ng < N) ? 16 : 0);
        }
        asm volatile("cp.async.commit_group;" ::: "memory");
    };

    prefetch(0);
    if (niter > 1) prefetch(1); else asm volatile("cp.async.commit_group;" ::: "memory");

#pragma unroll 1
    for (int i = 0; i < niter; i++) {
        asm volatile("cp.async.wait_group 1;" ::: "memory");
        __syncthreads();
        if (i + 2 < niter) prefetch(i + 2);
        else asm volatile("cp.async.commit_group;" ::: "memory");

        const uint32_t sA = sb + (i % NSTAGE) * STG;
        const uint32_t sB = sA + A_BYTES;
#pragma unroll
        for (int ks = 0; ks < 4; ks++) {
            uint32_t a[4][4];
#pragma unroll
            for (int mi = 0; mi < 4; mi++) {
                const uint32_t ab = sA + (2 * ks) * 2048 + (wm + mi * 16 + g) * 16 + c * 4;
                asm volatile("ld.shared.b32 %0, [%1];" : "=r"(a[mi][0]) : "r"(ab));
                asm volatile("ld.shared.b32 %0, [%1];" : "=r"(a[mi][1]) : "r"(ab + 128));
                asm volatile("ld.shared.b32 %0, [%1];" : "=r"(a[mi][2]) : "r"(ab + 2048));
                asm volatile("ld.shared.b32 %0, [%1];" : "=r"(a[mi][3]) : "r"(ab + 2176));
            }
#pragma unroll
            for (int ni = 0; ni < 4; ni++) {
                const uint32_t bb = sB + (2 * ks) * 2048 + (wn + ni * 8 + g) * 16 + c * 4;
                uint32_t b0, b1;
                asm volatile("ld.shared.b32 %0, [%1];" : "=r"(b0) : "r"(bb));
                asm volatile("ld.shared.b32 %0, [%1];" : "=r"(b1) : "r"(bb + 2048));
#pragma unroll
                for (int mi = 0; mi < 4; mi++) {
                    asm volatile(
                        "mma.sync.aligned.m16n8k8.row.col.f32.tf32.tf32.f32 "
                        "{%0,%1,%2,%3}, {%4,%5,%6,%7}, {%8,%9}, {%0,%1,%2,%3};"
                        : "+f"(acc[mi][ni][0]), "+f"(acc[mi][ni][1]),
                          "+f"(acc[mi][ni][2]), "+f"(acc[mi][ni][3])
                        : "r"(a[mi][0]), "r"(a[mi][1]), "r"(a[mi][2]), "r"(a[mi][3]),
                          "r"(b0), "r"(b1));
                }
            }
        }
    }

#pragma unroll
    for (int mi = 0; mi < 4; mi++) {
        const int row0 = bm + wm + mi * 16 + g;
#pragma unroll
        for (int ni = 0; ni < 4; ni++) {
            const int col = bn + wn + ni * 8 + c * 2;
            if (col < N) {
                *reinterpret_cast<float2*>(&C[(size_t)row0 * N + col]) =
                    make_float2(acc[mi][ni][0], acc[mi][ni][1]);
                *reinterpret_cast<float2*>(&C[(size_t)(row0 + 8) * N + col]) =
                    make_float2(acc[mi][ni][2], acc[mi][ni][3]);
            }
        }
    }
}

// ---------------- tf32 pre-rounding (RNA) ------------------------------------
__global__ void round_tf32_kernel(const float4* __restrict__ src,
                                  float4* __restrict__ dst, int n4)
{
    const int i = blockIdx.x * blockDim.x + threadIdx.x;
    if (i >= n4) return;
    float4 v = src[i];
    dst[i] = make_float4(__uint_as_float(f2tf32(v.x)),
                         __uint_as_float(f2tf32(v.y)),
                         __uint_as_float(f2tf32(v.z)),
                         __uint_as_float(f2tf32(v.w)));
}

// ---------------- depthwise causal conv(4) + SiLU ----------------------------
__global__ void conv_silu_kernel(const float* __restrict__ zx,
                                 const float* __restrict__ cw,
                                 const float* __restrict__ cb,
                                 float* __restrict__ xBC)
{
    const int idx = blockIdx.x * blockDim.x + threadIdx.x;
    if (idx >= SEQLEN * CONVDIM) return;
    const int l = idx / CONVDIM;
    const int c = idx - l * CONVDIM;
    float a = cb[c];
    const float* col = zx + DINNER + c;
#pragma unroll
    for (int t = 0; t < 4; t++) {
        const int ll = l - 3 + t;
        if (ll >= 0) a = fmaf(col[(size_t)ll * DPROJ], cw[c * 4 + t], a);
    }
    const float sg = 1.f / (1.f + expf(-a));
    xBC[idx] = a * sg;
}

// ---------------- dt = softplus(raw + bias), dA = exp(dt * A) ----------------
__global__ void dt_kernel(const float* __restrict__ zx,
                          const float* __restrict__ dt_bias,
                          const float* __restrict__ A_log,
                          float* __restrict__ dt, float* __restrict__ dA)
{
    const int idx = blockIdx.x * blockDim.x + threadIdx.x;
    if (idx >= SEQLEN * NHEADS) return;
    const int l = idx >> 6;
    const int h = idx & 63;
    const float v = zx[(size_t)l * DPROJ + DINNER + CONVDIM + h] + dt_bias[h];
    const float d = (v > 20.f) ? v : log1pf(expf(v));
    dt[idx] = d;
    dA[idx] = expf(-d * expf(A_log[h]));
}

// ---------------- per-chunk total decay T[z,h] = exp(sum dt * A) -------------
__global__ void chunk_decay_kernel(const float* __restrict__ dt,
                                   const float* __restrict__ A_log,
                                   float* __restrict__ T)
{
    const int idx = blockIdx.x * blockDim.x + threadIdx.x;
    if (idx >= NCHUNK * NHEADS) return;
    const int z = idx >> 6;
    const int h = idx & 63;
    const float a = -expf(A_log[h]);
    float ssum = 0.f;
    for (int i = 0; i < CHUNK; i++)
        ssum += dt[(size_t)(z * CHUNK + i) * NHEADS + h];
    T[idx] = expf(ssum * a);
}

// ---- Phase A: per-chunk local state scan (zero init, states only) -----------
// block b: pblk=b&3, z=(b>>2)&15, h=b>>6.  128 thr: pl=tid>>3, ng=tid&7.
__global__ __launch_bounds__(128)
void scan_local_kernel(const float* __restrict__ xBC,
                       const float* __restrict__ dtv,
                       const float* __restrict__ dAv,
                       float* __restrict__ st)
{
    const int b    = blockIdx.x;
    const int pblk = b & 3;
    const int z    = (b >> 2) & 15;
    const int h    = b >> 6;
    const int tid  = threadIdx.x;
    const int pl   = tid >> 3;
    const int ng   = tid & 7;
    const int p    = pblk * 16 + pl;

    __shared__ float sB[8][128];
    __shared__ float sx[8][16];
    __shared__ float sdt[8];
    __shared__ float sda[8];

    float s[16];
#pragma unroll
    for (int j = 0; j < 16; j++) s[j] = 0.f;

    const int lbeg = z * CHUNK;
    for (int l0 = lbeg; l0 < lbeg + CHUNK; l0 += 8) {
        __syncthreads();
#pragma unroll
        for (int k = 0; k < 8; k++)
            sB[k][tid] = xBC[(size_t)(l0 + k) * CONVDIM + DINNER + tid];
        {
            const int tt = tid >> 4, pp = tid & 15;
            sx[tt][pp] = xBC[(size_t)(l0 + tt) * CONVDIM + h * HEADDIM + pblk * 16 + pp];
        }
        if (tid < 8)       sdt[tid]     = dtv[(l0 + tid) * NHEADS + h];
        else if (tid < 16) sda[tid - 8] = dAv[(l0 + tid - 8) * NHEADS + h];
        __syncthreads();

#pragma unroll
        for (int t = 0; t < 8; t++) {
            const float e  = sda[t];
            const float xp = sx[t][pl] * sdt[t];
#pragma unroll
            for (int j = 0; j < 16; j++)
                s[j] = fmaf(s[j], e, xp * sB[t][ng + (j << 3)]);
        }
    }

    float* dst = st + (((size_t)h * NCHUNK + z) * HEADDIM + p) * DSTATE;
#pragma unroll
    for (int j = 0; j < 16; j++) dst[ng + (j << 3)] = s[j];
}

// ---- Phase B: sequential combine over chunks (in-place local -> prev) -------
__global__ void combine_kernel(float* __restrict__ st, const float* __restrict__ T)
{
    const int idx = blockIdx.x * blockDim.x + threadIdx.x;
    if (idx >= NHEADS * HEADDIM * DSTATE) return;
    const int h  = idx / (HEADDIM * DSTATE);
    const int pn = idx - h * (HEADDIM * DSTATE);
    float run = 0.f;
#pragma unroll
    for (int z = 0; z < NCHUNK; z++) {
        const size_t o = ((size_t)h * NCHUNK + z) * HEADDIM * DSTATE + pn;
        const float tmp = st[o];
        st[o] = run;
        run = fmaf(run, T[z * NHEADS + h], tmp);
    }
}

// ---- Phase C: full scan within chunk, init from prev state ------------------
__global__ __launch_bounds__(128)
void scan_chunk_kernel(const float* __restrict__ xBC,
                       const float* __restrict__ dtv,
                       const float* __restrict__ dAv,
                       const float* __restrict__ Dvec,
                       const float* __restrict__ st,
                       float* __restrict__ y)
{
    const int b    = blockIdx.x;
    const int pblk = b & 3;
    const int z    = (b >> 2) & 15;
    const int h    = b >> 6;
    const int tid  = threadIdx.x;
    const int pl   = tid >> 3;
    const int ng   = tid & 7;
    const int p    = pblk * 16 + pl;
    const float Dh = Dvec[h];

    __shared__ float sB[8][128];
    __shared__ float sC[8][128];
    __shared__ float sx[8][16];
    __shared__ float sdt[8];
    __shared__ float sda[8];

    float s[16];
    const float* src = st + (((size_t)h * NCHUNK + z) * HEADDIM + p) * DSTATE;
#pragma unroll
    for (int j = 0; j < 16; j++) s[j] = src[ng + (j << 3)];

    const int lbeg = z * CHUNK;
    for (int l0 = lbeg; l0 < lbeg + CHUNK; l0 += 8) {
        __syncthreads();
#pragma unroll
        for (int k = 0; k < 8; k++) {
            const float* row = xBC + (size_t)(l0 + k) * CONVDIM;
            sB[k][tid] = row[DINNER + tid];
            sC[k][tid] = row[DINNER + DSTATE + tid];
        }
        {
            const int tt = tid >> 4, pp = tid & 15;
            sx[tt][pp] = xBC[(size_t)(l0 + tt) * CONVDIM + h * HEADDIM + pblk * 16 + pp];
        }
        if (tid < 8)       sdt[tid]     = dtv[(l0 + tid) * NHEADS + h];
        else if (tid < 16) sda[tid - 8] = dAv[(l0 + tid - 8) * NHEADS + h];
        __syncthreads();

#pragma unroll
        for (int t = 0; t < 8; t++) {
            const float e   = sda[t];
            const float xv  = sx[t][pl];
            const float xp  = xv * sdt[t];
            float accv = 0.f;
#pragma unroll
            for (int j = 0; j < 16; j++) {
                const int n = ng + (j << 3);
                const float sv = fmaf(s[j], e, xp * sB[t][n]);
                s[j] = sv;
                accv = fmaf(sC[t][n], sv, accv);
            }
            accv += __shfl_xor_sync(0xffffffffu, accv, 1);
            accv += __shfl_xor_sync(0xffffffffu, accv, 2);
            accv += __shfl_xor_sync(0xffffffffu, accv, 4);
            if (ng == 0)
                y[(size_t)(l0 + t) * DINNER + h * HEADDIM + p] = accv + xv * Dh;
        }
    }
}

// -------- gate (y * silu(z)) + RMSNorm, output pre-rounded to tf32 -----------
__global__ __launch_bounds__(256)
void gate_norm_kernel(const float* __restrict__ y, const float* __restrict__ zx,
                      const float* __restrict__ nw, float* __restrict__ yn)
{
    __shared__ float buf[DINNER];
    __shared__ float red[8];
    const int l = blockIdx.x, tid = threadIdx.x;
    const float* yrow = y + (size_t)l * DINNER;
    const float* zrow = zx + (size_t)l * DPROJ;

    float part = 0.f;
    for (int i = tid; i < DINNER; i += 256) {
        const float z = zrow[i];
        const float gg = z / (1.f + expf(-z));
        const float v = yrow[i] * gg;
        buf[i] = v;
        part = fmaf(v, v, part);
    }
#pragma unroll
    for (int o = 16; o; o >>= 1) part += __shfl_xor_sync(0xffffffffu, part, o);
    if ((tid & 31) == 0) red[tid >> 5] = part;
    __syncthreads();
    if (tid < 8) {
        float v = red[tid];
#pragma unroll
        for (int o = 4; o; o >>= 1) v += __shfl_xor_sync(0xffu, v, o);
        if (tid == 0) red[0] = v;
    }
    __syncthreads();
    const float r = rsqrtf(red[0] / (float)DINNER + 1e-5f);
    for (int i = tid; i < DINNER; i += 256)
        yn[(size_t)l * DINNER + i] =
            __uint_as_float(f2tf32(buf[i] * r * nw[i]));
}

// ---------------- launcher ---------------------------------------------------
extern "C" void kernel_launch(void* const* d_in, const int* in_sizes, int n_in,
                              void* d_out, int out_size)
{
    const float* u          = (const float*)d_in[0];
    const float* in_proj_w  = (const float*)d_in[1];
    const float* conv_w     = (const float*)d_in[2];
    const float* conv_b     = (const float*)d_in[3];
    const float* dt_bias    = (const float*)d_in[4];
    const float* A_log      = (const float*)d_in[5];
    const float* Dvec       = (const float*)d_in[6];
    const float* norm_w     = (const float*)d_in[7];
    const float* out_proj_w = (const float*)d_in[8];
    float* out = (float*)d_out;

    float *zx, *xBC, *dt, *dA, *y, *yn, *ur, *w1r, *w2r, *st, *T;
    cudaGetSymbolAddress((void**)&zx,  g_zxbcdt);
    cudaGetSymbolAddress((void**)&xBC, g_xBC);
    cudaGetSymbolAddress((void**)&dt,  g_dt);
    cudaGetSymbolAddress((void**)&dA,  g_dA);
    cudaGetSymbolAddress((void**)&y,   g_y);
    cudaGetSymbolAddress((void**)&yn,  g_yn);
    cudaGetSymbolAddress((void**)&ur,  g_ur);
    cudaGetSymbolAddress((void**)&w1r, g_w1r);
    cudaGetSymbolAddress((void**)&w2r, g_w2r);
    cudaGetSymbolAddress((void**)&st,  g_st);
    cudaGetSymbolAddress((void**)&T,   g_T);

    cudaFuncSetAttribute(mma2_gemm,
                         cudaFuncAttributeMaxDynamicSharedMemorySize, GSMEM);

    // 0) pre-round activations + weights to tf32-representable fp32
    {
        const int n4u = SEQLEN * DMODEL / 4;
        const int n41 = DPROJ * DMODEL / 4;
        const int n42 = DMODEL * DINNER / 4;
        round_tf32_kernel<<<(n4u + 255) / 256, 256>>>((const float4*)u,  (float4*)ur,  n4u);
        round_tf32_kernel<<<(n41 + 255) / 256, 256>>>((const float4*)in_proj_w, (float4*)w1r, n41);
        round_tf32_kernel<<<(n42 + 255) / 256, 256>>>((const float4*)out_proj_w, (float4*)w2r, n42);
    }

    // 1) zxbcdt = u @ in_proj_w^T
    mma2_gemm<<<dim3((DPROJ + 127) / 128, SEQLEN / 128), 256, GSMEM>>>(
        ur, w1r, zx, SEQLEN, DPROJ, DMODEL);

    // 2) causal depthwise conv + SiLU
    conv_silu_kernel<<<(SEQLEN * CONVDIM + 255) / 256, 256>>>(
        zx, conv_w, conv_b, xBC);

    // 3) dt / decay precompute + per-chunk decay totals
    dt_kernel<<<(SEQLEN * NHEADS + 255) / 256, 256>>>(
        zx, dt_bias, A_log, dt, dA);
    chunk_decay_kernel<<<(NCHUNK * NHEADS + 255) / 256, 256>>>(dt, A_log, T);

    // 4) chunked selective scan: local states -> combine -> full scan
    scan_local_kernel<<<NHEADS * NCHUNK * 4, 128>>>(xBC, dt, dA, st);
    combine_kernel<<<(NHEADS * HEADDIM * DSTATE + 255) / 256, 256>>>(st, T);
    scan_chunk_kernel<<<NHEADS * NCHUNK * 4, 128>>>(xBC, dt, dA, Dvec, st, y);

    // 5) gate + RMSNorm (emits tf32-rounded yn)
    gate_norm_kernel<<<SEQLEN, 256>>>(y, zx, norm_w, yn);

    // 6) out = yn @ out_proj_w^T
    mma2_gemm<<<dim3(DMODEL / 128, SEQLEN / 128), 256, GSMEM>>>(
        yn, w2r, out, SEQLEN, DMODEL, DINNER);
}